// round 1
// baseline (speedup 1.0000x reference)
#include <cuda_runtime.h>
#include <cuda_bf16.h>
#include <mma.h>
#include <math.h>

using namespace nvcuda;

// Problem constants
#define BATCH 4
#define SEQ   1024
#define DMODEL 4096
#define KVDIM 512
#define NHEAD 32
#define NKV   4
#define HDIM  128
#define MROWS (BATCH*SEQ)   // 4096

// ---------------- scratch (no allocs allowed) ----------------
__device__ float g_Q[MROWS * DMODEL];   // 64MB
__device__ float g_K[MROWS * KVDIM];    // 8MB
__device__ float g_V[MROWS * KVDIM];    // 8MB
__device__ float g_O[MROWS * DMODEL];   // 64MB

// ---------------- GEMM: C = A(MxK) * B(KxN), bf16x3 split, fp32 accum ----
// block tile 128x128, k-tile 16, 8 warps (4x2), each warp 32x64 (2x4 frags)
#define SA_LD 24
#define SB_LD 136

__global__ void __launch_bounds__(256) gemm3x_kernel(
    const float* __restrict__ A, const float* __restrict__ Bm,
    float* __restrict__ C, int M, int Nn, int K)
{
    __shared__ __nv_bfloat16 sAh[128 * SA_LD];
    __shared__ __nv_bfloat16 sAl[128 * SA_LD];
    __shared__ __nv_bfloat16 sBh[16 * SB_LD];
    __shared__ __nv_bfloat16 sBl[16 * SB_LD];

    const int bm = blockIdx.y * 128;
    const int bn = blockIdx.x * 128;
    const int tid = threadIdx.x;
    const int warp = tid >> 5;
    const int wr = (warp >> 1) * 32;   // warp row: 0,32,64,96
    const int wc = (warp & 1) * 64;    // warp col: 0,64

    wmma::fragment<wmma::accumulator, 16, 16, 16, float> acc[2][4];
    #pragma unroll
    for (int i = 0; i < 2; i++)
        #pragma unroll
        for (int j = 0; j < 4; j++)
            wmma::fill_fragment(acc[i][j], 0.0f);

    for (int k0 = 0; k0 < K; k0 += 16) {
        __syncthreads();
        // Load A tile (128 x 16 fp32) -> hi/lo bf16
        #pragma unroll
        for (int it = 0; it < 2; ++it) {
            int idx = tid + it * 256;            // 0..511 float4s
            int r = idx >> 2;
            int c = (idx & 3) << 2;
            float4 v = *(const float4*)(A + (size_t)(bm + r) * K + k0 + c);
            __nv_bfloat16 hx = __float2bfloat16(v.x);
            __nv_bfloat16 hy = __float2bfloat16(v.y);
            __nv_bfloat16 hz = __float2bfloat16(v.z);
            __nv_bfloat16 hw = __float2bfloat16(v.w);
            __nv_bfloat16 lx = __float2bfloat16(v.x - __bfloat162float(hx));
            __nv_bfloat16 ly = __float2bfloat16(v.y - __bfloat162float(hy));
            __nv_bfloat16 lz = __float2bfloat16(v.z - __bfloat162float(hz));
            __nv_bfloat16 lw = __float2bfloat16(v.w - __bfloat162float(hw));
            __nv_bfloat162* dh = (__nv_bfloat162*)(sAh + r * SA_LD + c);
            __nv_bfloat162* dl = (__nv_bfloat162*)(sAl + r * SA_LD + c);
            dh[0] = __halves2bfloat162(hx, hy); dh[1] = __halves2bfloat162(hz, hw);
            dl[0] = __halves2bfloat162(lx, ly); dl[1] = __halves2bfloat162(lz, lw);
        }
        // Load B tile (16 x 128 fp32) -> hi/lo bf16
        #pragma unroll
        for (int it = 0; it < 2; ++it) {
            int idx = tid + it * 256;
            int r = idx >> 5;
            int c = (idx & 31) << 2;
            float4 v = *(const float4*)(Bm + (size_t)(k0 + r) * Nn + bn + c);
            __nv_bfloat16 hx = __float2bfloat16(v.x);
            __nv_bfloat16 hy = __float2bfloat16(v.y);
            __nv_bfloat16 hz = __float2bfloat16(v.z);
            __nv_bfloat16 hw = __float2bfloat16(v.w);
            __nv_bfloat16 lx = __float2bfloat16(v.x - __bfloat162float(hx));
            __nv_bfloat16 ly = __float2bfloat16(v.y - __bfloat162float(hy));
            __nv_bfloat16 lz = __float2bfloat16(v.z - __bfloat162float(hz));
            __nv_bfloat16 lw = __float2bfloat16(v.w - __bfloat162float(hw));
            __nv_bfloat162* dh = (__nv_bfloat162*)(sBh + r * SB_LD + c);
            __nv_bfloat162* dl = (__nv_bfloat162*)(sBl + r * SB_LD + c);
            dh[0] = __halves2bfloat162(hx, hy); dh[1] = __halves2bfloat162(hz, hw);
            dl[0] = __halves2bfloat162(lx, ly); dl[1] = __halves2bfloat162(lz, lw);
        }
        __syncthreads();

        wmma::fragment<wmma::matrix_a, 16, 16, 16, __nv_bfloat16, wmma::row_major> ah[2], al[2];
        wmma::fragment<wmma::matrix_b, 16, 16, 16, __nv_bfloat16, wmma::row_major> bh[4], bl[4];
        #pragma unroll
        for (int i = 0; i < 2; i++) {
            wmma::load_matrix_sync(ah[i], sAh + (wr + i * 16) * SA_LD, SA_LD);
            wmma::load_matrix_sync(al[i], sAl + (wr + i * 16) * SA_LD, SA_LD);
        }
        #pragma unroll
        for (int j = 0; j < 4; j++) {
            wmma::load_matrix_sync(bh[j], sBh + wc + j * 16, SB_LD);
            wmma::load_matrix_sync(bl[j], sBl + wc + j * 16, SB_LD);
        }
        #pragma unroll
        for (int i = 0; i < 2; i++)
            #pragma unroll
            for (int j = 0; j < 4; j++) {
                wmma::mma_sync(acc[i][j], ah[i], bh[j], acc[i][j]);
                wmma::mma_sync(acc[i][j], ah[i], bl[j], acc[i][j]);
                wmma::mma_sync(acc[i][j], al[i], bh[j], acc[i][j]);
            }
    }

    #pragma unroll
    for (int i = 0; i < 2; i++)
        #pragma unroll
        for (int j = 0; j < 4; j++)
            wmma::store_matrix_sync(C + (size_t)(bm + wr + i * 16) * Nn + bn + wc + j * 16,
                                    acc[i][j], Nn, wmma::mem_row_major);
}

// ---------------- RoPE + bias (in place) --------------------------------
// X: [MROWS, width] row-major. bias added BEFORE rotation.
__global__ void rope_bias_kernel(float* __restrict__ X, const float* __restrict__ bias,
                                 int width, int total_pairs)
{
    int idx = blockIdx.x * blockDim.x + threadIdx.x;
    if (idx >= total_pairs) return;
    int ppr = width >> 1;
    int row = idx / ppr;
    int p = idx - row * ppr;
    int i = p & 63;                 // pair index within head
    int pos = row & (SEQ - 1);
    float freq = exp2f(-(float)i * 0.20762050593434293f);  // log2(10000)/64
    float ang = (float)pos * freq;
    float sv, cv;
    sincosf(ang, &sv, &cv);
    float2 q = *(float2*)(X + (size_t)row * width + 2 * p);
    float e = q.x + bias[2 * p];
    float o = q.y + bias[2 * p + 1];
    float2 r2 = make_float2(e * cv - o * sv, o * cv + e * sv);
    *(float2*)(X + (size_t)row * width + 2 * p) = r2;
}

// ---------------- bias add (vectorized) ----------------------------------
__global__ void bias_add4_kernel(float* __restrict__ X, const float* __restrict__ b,
                                 int width, int total4)
{
    int idx = blockIdx.x * blockDim.x + threadIdx.x;
    if (idx >= total4) return;
    int c = (idx << 2) % width;
    float4 v = ((float4*)X)[idx];
    float4 bb = *(const float4*)(b + c);
    v.x += bb.x; v.y += bb.y; v.z += bb.z; v.w += bb.w;
    ((float4*)X)[idx] = v;
}

// ---------------- flash attention (fp32) ---------------------------------
// grid: (SEQ/64, BATCH*NHEAD), block 256 (8 warps).
// warp w owns q-rows w*8..w*8+7; lane owns score cols {lane, lane+32},
// O cols lane*4..lane*4+3.
#define SKLD 132
#define ATT_SMEM ((64*128 + 64*SKLD + 64*128 + 64*64) * 4)

__global__ void __launch_bounds__(256) flash_attn_kernel(
    const float* __restrict__ Q, const float* __restrict__ K,
    const float* __restrict__ V, float* __restrict__ O)
{
    extern __shared__ float sm[];
    float* sQ = sm;                    // 64*128
    float* sK = sQ + 64 * 128;         // 64*SKLD (padded)
    float* sV = sK + 64 * SKLD;        // 64*128
    float* sP = sV + 64 * 128;         // 64*64

    const int b = blockIdx.y >> 5;
    const int h = blockIdx.y & 31;
    const int kh = h & 3;              // kv head = H % NUM_HEAD_KV
    const int q0 = blockIdx.x * 64;
    const int tid = threadIdx.x;
    const int lane = tid & 31;
    const int warp = tid >> 5;
    const float scale = 0.08838834764831843f;  // 1/sqrt(128)

    // load Q tile, pre-scaled
    for (int idx = tid; idx < 64 * 32; idx += 256) {
        int r = idx >> 5, c4 = (idx & 31) << 2;
        float4 v = *(const float4*)(Q + ((size_t)(b * SEQ + q0 + r)) * DMODEL + h * HDIM + c4);
        v.x *= scale; v.y *= scale; v.z *= scale; v.w *= scale;
        *(float4*)(sQ + r * 128 + c4) = v;
    }

    float acc[8][4];
    float mrow[8], lrow[8];
    #pragma unroll
    for (int i = 0; i < 8; i++) {
        mrow[i] = -1e30f; lrow[i] = 0.f;
        acc[i][0] = acc[i][1] = acc[i][2] = acc[i][3] = 0.f;
    }

    for (int j = 0; j <= blockIdx.x; ++j) {
        const int k0 = j * 64;
        __syncthreads();
        for (int idx = tid; idx < 64 * 32; idx += 256) {
            int r = idx >> 5, c4 = (idx & 31) << 2;
            size_t off = ((size_t)(b * SEQ + k0 + r)) * KVDIM + kh * HDIM + c4;
            *(float4*)(sK + r * SKLD + c4) = *(const float4*)(K + off);
            *(float4*)(sV + r * 128 + c4) = *(const float4*)(V + off);
        }
        __syncthreads();

        float s0[8], s1[8];
        #pragma unroll
        for (int i = 0; i < 8; i++) { s0[i] = 0.f; s1[i] = 0.f; }
        #pragma unroll 2
        for (int k = 0; k < 128; k += 4) {
            float4 ka = *(float4*)(sK + lane * SKLD + k);
            float4 kb = *(float4*)(sK + (lane + 32) * SKLD + k);
            #pragma unroll
            for (int i = 0; i < 8; i++) {
                float4 qv = *(float4*)(sQ + (warp * 8 + i) * 128 + k);
                s0[i] += qv.x * ka.x + qv.y * ka.y + qv.z * ka.z + qv.w * ka.w;
                s1[i] += qv.x * kb.x + qv.y * kb.y + qv.z * kb.z + qv.w * kb.w;
            }
        }
        if (j == blockIdx.x) {   // diagonal tile: mask col > row (k0 == q0)
            #pragma unroll
            for (int i = 0; i < 8; i++) {
                int qr = warp * 8 + i;
                if (lane > qr)      s0[i] = -1e30f;
                if (lane + 32 > qr) s1[i] = -1e30f;
            }
        }
        // online softmax (rows of one warp live in that warp)
        #pragma unroll
        for (int i = 0; i < 8; i++) {
            float mx = fmaxf(s0[i], s1[i]);
            #pragma unroll
            for (int off = 16; off; off >>= 1)
                mx = fmaxf(mx, __shfl_xor_sync(0xffffffffu, mx, off));
            float mnew = fmaxf(mrow[i], mx);
            float p0 = __expf(s0[i] - mnew);
            float p1 = __expf(s1[i] - mnew);
            float alpha = __expf(mrow[i] - mnew);
            mrow[i] = mnew;
            float ps = p0 + p1;
            #pragma unroll
            for (int off = 16; off; off >>= 1)
                ps += __shfl_xor_sync(0xffffffffu, ps, off);
            lrow[i] = lrow[i] * alpha + ps;
            acc[i][0] *= alpha; acc[i][1] *= alpha;
            acc[i][2] *= alpha; acc[i][3] *= alpha;
            sP[(warp * 8 + i) * 64 + lane] = p0;
            sP[(warp * 8 + i) * 64 + lane + 32] = p1;
        }
        __syncthreads();
        // O += P * V
        for (int c = 0; c < 64; c++) {
            float4 vv = *(float4*)(sV + c * 128 + lane * 4);
            #pragma unroll
            for (int i = 0; i < 8; i++) {
                float p = sP[(warp * 8 + i) * 64 + c];
                acc[i][0] += p * vv.x; acc[i][1] += p * vv.y;
                acc[i][2] += p * vv.z; acc[i][3] += p * vv.w;
            }
        }
    }

    #pragma unroll
    for (int i = 0; i < 8; i++) {
        float inv = 1.f / lrow[i];
        float4 o4 = make_float4(acc[i][0] * inv, acc[i][1] * inv,
                                acc[i][2] * inv, acc[i][3] * inv);
        int r = q0 + warp * 8 + i;
        *(float4*)(O + ((size_t)(b * SEQ + r)) * DMODEL + h * HDIM + lane * 4) = o4;
    }
}

// ---------------- launch ---------------------------------------------------
extern "C" void kernel_launch(void* const* d_in, const int* in_sizes, int n_in,
                              void* d_out, int out_size)
{
    const float* x  = (const float*)d_in[0];
    const float* Wq = (const float*)d_in[1];
    const float* bq = (const float*)d_in[2];
    const float* Wk = (const float*)d_in[3];
    const float* bk = (const float*)d_in[4];
    const float* Wv = (const float*)d_in[5];
    const float* bv = (const float*)d_in[6];
    const float* Wo = (const float*)d_in[7];
    const float* bo = (const float*)d_in[8];
    float* out = (float*)d_out;

    float *Qp, *Kp, *Vp, *Op;
    cudaGetSymbolAddress((void**)&Qp, g_Q);
    cudaGetSymbolAddress((void**)&Kp, g_K);
    cudaGetSymbolAddress((void**)&Vp, g_V);
    cudaGetSymbolAddress((void**)&Op, g_O);

    dim3 blk(256);

    // QKV projections
    gemm3x_kernel<<<dim3(DMODEL / 128, MROWS / 128), blk>>>(x, Wq, Qp, MROWS, DMODEL, DMODEL);
    gemm3x_kernel<<<dim3(KVDIM / 128,  MROWS / 128), blk>>>(x, Wk, Kp, MROWS, KVDIM, DMODEL);
    gemm3x_kernel<<<dim3(KVDIM / 128,  MROWS / 128), blk>>>(x, Wv, Vp, MROWS, KVDIM, DMODEL);

    // bias + RoPE for Q/K, bias for V
    {
        int tpQ = MROWS * (DMODEL / 2);
        rope_bias_kernel<<<(tpQ + 255) / 256, 256>>>(Qp, bq, DMODEL, tpQ);
        int tpK = MROWS * (KVDIM / 2);
        rope_bias_kernel<<<(tpK + 255) / 256, 256>>>(Kp, bk, KVDIM, tpK);
        int t4 = MROWS * KVDIM / 4;
        bias_add4_kernel<<<(t4 + 255) / 256, 256>>>(Vp, bv, KVDIM, t4);
    }

    // attention
    cudaFuncSetAttribute(flash_attn_kernel, cudaFuncAttributeMaxDynamicSharedMemorySize, ATT_SMEM);
    flash_attn_kernel<<<dim3(SEQ / 64, BATCH * NHEAD), 256, ATT_SMEM>>>(Qp, Kp, Vp, Op);

    // output projection + bias
    gemm3x_kernel<<<dim3(DMODEL / 128, MROWS / 128), blk>>>(Op, Wo, out, MROWS, DMODEL, DMODEL);
    {
        int t4 = MROWS * DMODEL / 4;
        bias_add4_kernel<<<(t4 + 255) / 256, 256>>>(out, bo, DMODEL, t4);
    }
}

// round 2
// speedup vs baseline: 1.1271x; 1.1271x over previous
#include <cuda_runtime.h>
#include <cuda_bf16.h>
#include <mma.h>
#include <math.h>
#include <stdint.h>

using namespace nvcuda;

#define BATCH 4
#define SEQ   1024
#define DMODEL 4096
#define KVDIM 512
#define NHEAD 32
#define HDIM  128
#define MROWS (BATCH*SEQ)   // 4096

// ---------------- scratch ----------------
__device__ float g_Q[MROWS * DMODEL];
__device__ float g_K[MROWS * KVDIM];
__device__ float g_V[MROWS * KVDIM];
__device__ __nv_bfloat16 g_xh[MROWS * DMODEL],  g_xl[MROWS * DMODEL];
__device__ __nv_bfloat16 g_wqh[DMODEL * DMODEL], g_wql[DMODEL * DMODEL];
__device__ __nv_bfloat16 g_wkh[DMODEL * KVDIM],  g_wkl[DMODEL * KVDIM];
__device__ __nv_bfloat16 g_wvh[DMODEL * KVDIM],  g_wvl[DMODEL * KVDIM];
__device__ __nv_bfloat16 g_woh[DMODEL * DMODEL], g_wol[DMODEL * DMODEL];
__device__ __nv_bfloat16 g_oh[MROWS * DMODEL],   g_ol[MROWS * DMODEL];

// ---------------- fp32 -> bf16 hi/lo split ----------------
__global__ void split_kernel(const float* __restrict__ src,
                             __nv_bfloat16* __restrict__ hi,
                             __nv_bfloat16* __restrict__ lo, int n4)
{
    int idx = blockIdx.x * blockDim.x + threadIdx.x;
    if (idx >= n4) return;
    float4 v = ((const float4*)src)[idx];
    __nv_bfloat16 h0 = __float2bfloat16(v.x);
    __nv_bfloat16 h1 = __float2bfloat16(v.y);
    __nv_bfloat16 h2 = __float2bfloat16(v.z);
    __nv_bfloat16 h3 = __float2bfloat16(v.w);
    __nv_bfloat162 H0 = __halves2bfloat162(h0, h1);
    __nv_bfloat162 H1 = __halves2bfloat162(h2, h3);
    __nv_bfloat162 L0 = __halves2bfloat162(__float2bfloat16(v.x - __bfloat162float(h0)),
                                           __float2bfloat16(v.y - __bfloat162float(h1)));
    __nv_bfloat162 L1 = __halves2bfloat162(__float2bfloat16(v.z - __bfloat162float(h2)),
                                           __float2bfloat16(v.w - __bfloat162float(h3)));
    ((__nv_bfloat162*)hi)[idx * 2]     = H0;
    ((__nv_bfloat162*)hi)[idx * 2 + 1] = H1;
    ((__nv_bfloat162*)lo)[idx * 2]     = L0;
    ((__nv_bfloat162*)lo)[idx * 2 + 1] = L1;
}

// ---------------- pipelined bf16x3 GEMM ----------------
// C = (Ah+Al)(Bh+Bl) dropping Al*Bl. BM=BN=128, BK=32, 8 warps (2x4),
// warp tile 64x32. 2-stage cp.async double buffering.
#define SA_LD 40
#define SB_LD 136
#define STAGE_ELEMS (2*128*SA_LD + 2*32*SB_LD)   // 18944
#define GEMM_SMEM (2 * STAGE_ELEMS * 2)          // bytes = 75776

__device__ __forceinline__ void cp16(void* s, const void* g)
{
    uint32_t sa = (uint32_t)__cvta_generic_to_shared(s);
    asm volatile("cp.async.cg.shared.global [%0], [%1], 16;\n" :: "r"(sa), "l"(g));
}

__global__ void __launch_bounds__(256) gemm_sp_kernel(
    const __nv_bfloat16* __restrict__ Ah, const __nv_bfloat16* __restrict__ Al,
    const __nv_bfloat16* __restrict__ Bh, const __nv_bfloat16* __restrict__ Bl,
    float* __restrict__ C, int M, int Nn, int K)
{
    extern __shared__ __nv_bfloat16 smbuf[];
    const int bm = blockIdx.y * 128;
    const int bn = blockIdx.x * 128;
    const int tid = threadIdx.x;
    const int warp = tid >> 5;
    const int wr = (warp >> 2) * 64;   // 0,64
    const int wc = (warp & 3) * 32;    // 0,32,64,96

    wmma::fragment<wmma::accumulator, 16, 16, 16, float> acc[4][2];
    #pragma unroll
    for (int i = 0; i < 4; i++)
        #pragma unroll
        for (int j = 0; j < 2; j++)
            wmma::fill_fragment(acc[i][j], 0.0f);

    // per-thread load coordinates
    const int ar[2] = { tid >> 2, (tid + 256) >> 2 };
    const int ac[2] = { (tid & 3) << 3, (tid & 3) << 3 };
    const int br[2] = { tid >> 4, (tid + 256) >> 4 };
    const int bc[2] = { (tid & 15) << 3, (tid & 15) << 3 };

    auto load_st = [&](int st, int k0) {
        __nv_bfloat16* s = smbuf + st * STAGE_ELEMS;
        #pragma unroll
        for (int it = 0; it < 2; ++it) {
            int r = ar[it], c = ac[it];
            cp16(s + r * SA_LD + c,                     Ah + (size_t)(bm + r) * K + k0 + c);
            cp16(s + 128 * SA_LD + r * SA_LD + c,       Al + (size_t)(bm + r) * K + k0 + c);
            int rb = br[it], cb = bc[it];
            cp16(s + 2 * 128 * SA_LD + rb * SB_LD + cb, Bh + (size_t)(k0 + rb) * Nn + bn + cb);
            cp16(s + 2 * 128 * SA_LD + 32 * SB_LD + rb * SB_LD + cb,
                                                        Bl + (size_t)(k0 + rb) * Nn + bn + cb);
        }
        asm volatile("cp.async.commit_group;\n");
    };

    const int ntiles = K >> 5;
    load_st(0, 0);

    for (int kt = 0; kt < ntiles; ++kt) {
        if (kt + 1 < ntiles) {
            load_st((kt + 1) & 1, (kt + 1) << 5);
            asm volatile("cp.async.wait_group 1;\n");
        } else {
            asm volatile("cp.async.wait_group 0;\n");
        }
        __syncthreads();

        __nv_bfloat16* s   = smbuf + (kt & 1) * STAGE_ELEMS;
        __nv_bfloat16* sAh = s;
        __nv_bfloat16* sAl = s + 128 * SA_LD;
        __nv_bfloat16* sBh = s + 2 * 128 * SA_LD;
        __nv_bfloat16* sBl = sBh + 32 * SB_LD;

        #pragma unroll
        for (int kk = 0; kk < 32; kk += 16) {
            wmma::fragment<wmma::matrix_a, 16, 16, 16, __nv_bfloat16, wmma::row_major> ah[4], al[4];
            wmma::fragment<wmma::matrix_b, 16, 16, 16, __nv_bfloat16, wmma::row_major> bh[2], bl[2];
            #pragma unroll
            for (int i = 0; i < 4; i++) {
                wmma::load_matrix_sync(ah[i], sAh + (wr + i * 16) * SA_LD + kk, SA_LD);
                wmma::load_matrix_sync(al[i], sAl + (wr + i * 16) * SA_LD + kk, SA_LD);
            }
            #pragma unroll
            for (int j = 0; j < 2; j++) {
                wmma::load_matrix_sync(bh[j], sBh + kk * SB_LD + wc + j * 16, SB_LD);
                wmma::load_matrix_sync(bl[j], sBl + kk * SB_LD + wc + j * 16, SB_LD);
            }
            #pragma unroll
            for (int i = 0; i < 4; i++)
                #pragma unroll
                for (int j = 0; j < 2; j++) {
                    wmma::mma_sync(acc[i][j], ah[i], bh[j], acc[i][j]);
                    wmma::mma_sync(acc[i][j], ah[i], bl[j], acc[i][j]);
                    wmma::mma_sync(acc[i][j], al[i], bh[j], acc[i][j]);
                }
        }
        __syncthreads();
    }

    #pragma unroll
    for (int i = 0; i < 4; i++)
        #pragma unroll
        for (int j = 0; j < 2; j++)
            wmma::store_matrix_sync(C + (size_t)(bm + wr + i * 16) * Nn + bn + wc + j * 16,
                                    acc[i][j], Nn, wmma::mem_row_major);
}

// ---------------- RoPE + bias (in place, fp32) ----------------
__global__ void rope_bias_kernel(float* __restrict__ X, const float* __restrict__ bias,
                                 int width, int total_pairs)
{
    int idx = blockIdx.x * blockDim.x + threadIdx.x;
    if (idx >= total_pairs) return;
    int ppr = width >> 1;
    int row = idx / ppr;
    int p = idx - row * ppr;
    int i = p & 63;
    int pos = row & (SEQ - 1);
    float freq = exp2f(-(float)i * 0.20762050593434293f);
    float ang = (float)pos * freq;
    float sv, cv;
    sincosf(ang, &sv, &cv);
    float2 q = *(float2*)(X + (size_t)row * width + 2 * p);
    float e = q.x + bias[2 * p];
    float o = q.y + bias[2 * p + 1];
    float2 r2 = make_float2(e * cv - o * sv, o * cv + e * sv);
    *(float2*)(X + (size_t)row * width + 2 * p) = r2;
}

__global__ void bias_add4_kernel(float* __restrict__ X, const float* __restrict__ b,
                                 int width, int total4)
{
    int idx = blockIdx.x * blockDim.x + threadIdx.x;
    if (idx >= total4) return;
    int c = (idx << 2) % width;
    float4 v = ((float4*)X)[idx];
    float4 bb = *(const float4*)(b + c);
    v.x += bb.x; v.y += bb.y; v.z += bb.z; v.w += bb.w;
    ((float4*)X)[idx] = v;
}

// ---------------- flash attention (fp32, bf16 hi/lo output) ----------------
#define SKLD 132
#define ATT_SMEM ((64*128 + 64*SKLD + 64*128 + 64*64) * 4)

__global__ void __launch_bounds__(256) flash_attn_kernel(
    const float* __restrict__ Q, const float* __restrict__ K,
    const float* __restrict__ V,
    __nv_bfloat16* __restrict__ Ohi, __nv_bfloat16* __restrict__ Olo)
{
    extern __shared__ float sm[];
    float* sQ = sm;
    float* sK = sQ + 64 * 128;
    float* sV = sK + 64 * SKLD;
    float* sP = sV + 64 * 128;

    const int b = blockIdx.y >> 5;
    const int h = blockIdx.y & 31;
    const int kh = h & 3;
    const int q0 = blockIdx.x * 64;
    const int tid = threadIdx.x;
    const int lane = tid & 31;
    const int warp = tid >> 5;
    const float scale = 0.08838834764831843f;

    for (int idx = tid; idx < 64 * 32; idx += 256) {
        int r = idx >> 5, c4 = (idx & 31) << 2;
        float4 v = *(const float4*)(Q + ((size_t)(b * SEQ + q0 + r)) * DMODEL + h * HDIM + c4);
        v.x *= scale; v.y *= scale; v.z *= scale; v.w *= scale;
        *(float4*)(sQ + r * 128 + c4) = v;
    }

    float acc[8][4];
    float mrow[8], lrow[8];
    #pragma unroll
    for (int i = 0; i < 8; i++) {
        mrow[i] = -1e30f; lrow[i] = 0.f;
        acc[i][0] = acc[i][1] = acc[i][2] = acc[i][3] = 0.f;
    }

    for (int j = 0; j <= blockIdx.x; ++j) {
        const int k0 = j * 64;
        __syncthreads();
        for (int idx = tid; idx < 64 * 32; idx += 256) {
            int r = idx >> 5, c4 = (idx & 31) << 2;
            size_t off = ((size_t)(b * SEQ + k0 + r)) * KVDIM + kh * HDIM + c4;
            *(float4*)(sK + r * SKLD + c4) = *(const float4*)(K + off);
            *(float4*)(sV + r * 128 + c4) = *(const float4*)(V + off);
        }
        __syncthreads();

        float s0[8], s1[8];
        #pragma unroll
        for (int i = 0; i < 8; i++) { s0[i] = 0.f; s1[i] = 0.f; }
        #pragma unroll 2
        for (int k = 0; k < 128; k += 4) {
            float4 ka = *(float4*)(sK + lane * SKLD + k);
            float4 kb = *(float4*)(sK + (lane + 32) * SKLD + k);
            #pragma unroll
            for (int i = 0; i < 8; i++) {
                float4 qv = *(float4*)(sQ + (warp * 8 + i) * 128 + k);
                s0[i] += qv.x * ka.x + qv.y * ka.y + qv.z * ka.z + qv.w * ka.w;
                s1[i] += qv.x * kb.x + qv.y * kb.y + qv.z * kb.z + qv.w * kb.w;
            }
        }
        if (j == blockIdx.x) {
            #pragma unroll
            for (int i = 0; i < 8; i++) {
                int qr = warp * 8 + i;
                if (lane > qr)      s0[i] = -1e30f;
                if (lane + 32 > qr) s1[i] = -1e30f;
            }
        }
        #pragma unroll
        for (int i = 0; i < 8; i++) {
            float mx = fmaxf(s0[i], s1[i]);
            #pragma unroll
            for (int off = 16; off; off >>= 1)
                mx = fmaxf(mx, __shfl_xor_sync(0xffffffffu, mx, off));
            float mnew = fmaxf(mrow[i], mx);
            float p0 = __expf(s0[i] - mnew);
            float p1 = __expf(s1[i] - mnew);
            float alpha = __expf(mrow[i] - mnew);
            mrow[i] = mnew;
            float ps = p0 + p1;
            #pragma unroll
            for (int off = 16; off; off >>= 1)
                ps += __shfl_xor_sync(0xffffffffu, ps, off);
            lrow[i] = lrow[i] * alpha + ps;
            acc[i][0] *= alpha; acc[i][1] *= alpha;
            acc[i][2] *= alpha; acc[i][3] *= alpha;
            sP[(warp * 8 + i) * 64 + lane] = p0;
            sP[(warp * 8 + i) * 64 + lane + 32] = p1;
        }
        __syncthreads();
        for (int c = 0; c < 64; c++) {
            float4 vv = *(float4*)(sV + c * 128 + lane * 4);
            #pragma unroll
            for (int i = 0; i < 8; i++) {
                float p = sP[(warp * 8 + i) * 64 + c];
                acc[i][0] += p * vv.x; acc[i][1] += p * vv.y;
                acc[i][2] += p * vv.z; acc[i][3] += p * vv.w;
            }
        }
    }

    #pragma unroll
    for (int i = 0; i < 8; i++) {
        float inv = 1.f / lrow[i];
        float o0 = acc[i][0] * inv, o1 = acc[i][1] * inv;
        float o2 = acc[i][2] * inv, o3 = acc[i][3] * inv;
        int r = q0 + warp * 8 + i;
        size_t off = ((size_t)(b * SEQ + r)) * DMODEL + h * HDIM + lane * 4;
        __nv_bfloat16 h0 = __float2bfloat16(o0), h1 = __float2bfloat16(o1);
        __nv_bfloat16 h2 = __float2bfloat16(o2), h3 = __float2bfloat16(o3);
        ((__nv_bfloat162*)(Ohi + off))[0] = __halves2bfloat162(h0, h1);
        ((__nv_bfloat162*)(Ohi + off))[1] = __halves2bfloat162(h2, h3);
        ((__nv_bfloat162*)(Olo + off))[0] = __halves2bfloat162(
            __float2bfloat16(o0 - __bfloat162float(h0)),
            __float2bfloat16(o1 - __bfloat162float(h1)));
        ((__nv_bfloat162*)(Olo + off))[1] = __halves2bfloat162(
            __float2bfloat16(o2 - __bfloat162float(h2)),
            __float2bfloat16(o3 - __bfloat162float(h3)));
    }
}

// ---------------- launch ----------------
extern "C" void kernel_launch(void* const* d_in, const int* in_sizes, int n_in,
                              void* d_out, int out_size)
{
    const float* x  = (const float*)d_in[0];
    const float* Wq = (const float*)d_in[1];
    const float* bq = (const float*)d_in[2];
    const float* Wk = (const float*)d_in[3];
    const float* bk = (const float*)d_in[4];
    const float* Wv = (const float*)d_in[5];
    const float* bv = (const float*)d_in[6];
    const float* Wo = (const float*)d_in[7];
    const float* bo = (const float*)d_in[8];
    float* out = (float*)d_out;

    float *Qp, *Kp, *Vp;
    __nv_bfloat16 *xh, *xl, *wqh, *wql, *wkh, *wkl, *wvh, *wvl, *woh, *wol, *oh, *ol;
    cudaGetSymbolAddress((void**)&Qp, g_Q);
    cudaGetSymbolAddress((void**)&Kp, g_K);
    cudaGetSymbolAddress((void**)&Vp, g_V);
    cudaGetSymbolAddress((void**)&xh, g_xh);   cudaGetSymbolAddress((void**)&xl, g_xl);
    cudaGetSymbolAddress((void**)&wqh, g_wqh); cudaGetSymbolAddress((void**)&wql, g_wql);
    cudaGetSymbolAddress((void**)&wkh, g_wkh); cudaGetSymbolAddress((void**)&wkl, g_wkl);
    cudaGetSymbolAddress((void**)&wvh, g_wvh); cudaGetSymbolAddress((void**)&wvl, g_wvl);
    cudaGetSymbolAddress((void**)&woh, g_woh); cudaGetSymbolAddress((void**)&wol, g_wol);
    cudaGetSymbolAddress((void**)&oh, g_oh);   cudaGetSymbolAddress((void**)&ol, g_ol);

    cudaFuncSetAttribute(gemm_sp_kernel, cudaFuncAttributeMaxDynamicSharedMemorySize, GEMM_SMEM);
    cudaFuncSetAttribute(flash_attn_kernel, cudaFuncAttributeMaxDynamicSharedMemorySize, ATT_SMEM);

    // splits
    {
        int n4 = MROWS * DMODEL / 4;
        split_kernel<<<(n4 + 255) / 256, 256>>>(x, xh, xl, n4);
        n4 = DMODEL * DMODEL / 4;
        split_kernel<<<(n4 + 255) / 256, 256>>>(Wq, wqh, wql, n4);
        split_kernel<<<(n4 + 255) / 256, 256>>>(Wo, woh, wol, n4);
        n4 = DMODEL * KVDIM / 4;
        split_kernel<<<(n4 + 255) / 256, 256>>>(Wk, wkh, wkl, n4);
        split_kernel<<<(n4 + 255) / 256, 256>>>(Wv, wvh, wvl, n4);
    }

    // projections
    gemm_sp_kernel<<<dim3(DMODEL / 128, MROWS / 128), 256, GEMM_SMEM>>>(
        xh, xl, wqh, wql, Qp, MROWS, DMODEL, DMODEL);
    gemm_sp_kernel<<<dim3(KVDIM / 128, MROWS / 128), 256, GEMM_SMEM>>>(
        xh, xl, wkh, wkl, Kp, MROWS, KVDIM, DMODEL);
    gemm_sp_kernel<<<dim3(KVDIM / 128, MROWS / 128), 256, GEMM_SMEM>>>(
        xh, xl, wvh, wvl, Vp, MROWS, KVDIM, DMODEL);

    // bias + RoPE
    {
        int tpQ = MROWS * (DMODEL / 2);
        rope_bias_kernel<<<(tpQ + 255) / 256, 256>>>(Qp, bq, DMODEL, tpQ);
        int tpK = MROWS * (KVDIM / 2);
        rope_bias_kernel<<<(tpK + 255) / 256, 256>>>(Kp, bk, KVDIM, tpK);
        int t4 = MROWS * KVDIM / 4;
        bias_add4_kernel<<<(t4 + 255) / 256, 256>>>(Vp, bv, KVDIM, t4);
    }

    // attention
    flash_attn_kernel<<<dim3(SEQ / 64, BATCH * NHEAD), 256, ATT_SMEM>>>(Qp, Kp, Vp, oh, ol);

    // output projection + bias
    gemm_sp_kernel<<<dim3(DMODEL / 128, MROWS / 128), 256, GEMM_SMEM>>>(
        oh, ol, woh, wol, out, MROWS, DMODEL, DMODEL);
    {
        int t4 = MROWS * DMODEL / 4;
        bias_add4_kernel<<<(t4 + 255) / 256, 256>>>(out, bo, DMODEL, t4);
    }
}

// round 5
// speedup vs baseline: 1.7843x; 1.5831x over previous
#include <cuda_runtime.h>
#include <cuda_fp16.h>
#include <math.h>
#include <stdint.h>
#include <mma.h>

using namespace nvcuda;

#define BATCH 4
#define SEQ   1024
#define DMODEL 4096
#define KVDIM 512
#define NHEAD 32
#define HDIM  128
#define MROWS (BATCH*SEQ)   // 4096

// ---------------- scratch ----------------
__device__ float g_Q[MROWS * DMODEL];
__device__ float g_K[MROWS * KVDIM];
__device__ float g_V[MROWS * KVDIM];
__device__ __half g_xh[MROWS * DMODEL], g_xl[MROWS * DMODEL];
__device__ __half g_wq[DMODEL * DMODEL];
__device__ __half g_wk[DMODEL * KVDIM];
__device__ __half g_wv[DMODEL * KVDIM];
__device__ __half g_wo[DMODEL * DMODEL];
__device__ __half g_oh[MROWS * DMODEL], g_ol[MROWS * DMODEL];

// ---------------- fp32 -> fp16 hi/lo split ----------------
__global__ void split_half_kernel(const float* __restrict__ src,
                                  __half* __restrict__ hi,
                                  __half* __restrict__ lo, int n4)
{
    int idx = blockIdx.x * blockDim.x + threadIdx.x;
    if (idx >= n4) return;
    float4 v = ((const float4*)src)[idx];
    __half h0 = __float2half(v.x), h1 = __float2half(v.y);
    __half h2 = __float2half(v.z), h3 = __float2half(v.w);
    ((__half2*)hi)[idx * 2]     = __halves2half2(h0, h1);
    ((__half2*)hi)[idx * 2 + 1] = __halves2half2(h2, h3);
    ((__half2*)lo)[idx * 2]     = __halves2half2(
        __float2half(v.x - __half2float(h0)), __float2half(v.y - __half2float(h1)));
    ((__half2*)lo)[idx * 2 + 1] = __halves2half2(
        __float2half(v.z - __half2float(h2)), __float2half(v.w - __half2float(h3)));
}

// ---------------- fp32 -> fp16 (single) ----------------
__global__ void conv_half_kernel(const float* __restrict__ src,
                                 __half* __restrict__ dst, int n4)
{
    int idx = blockIdx.x * blockDim.x + threadIdx.x;
    if (idx >= n4) return;
    float4 v = ((const float4*)src)[idx];
    ((__half2*)dst)[idx * 2]     = __halves2half2(__float2half(v.x), __float2half(v.y));
    ((__half2*)dst)[idx * 2 + 1] = __halves2half2(__float2half(v.z), __float2half(v.w));
}

// ---------------- fp16x2 GEMM: C = (Ah+Al)[M,K] * B[K,N] ----------------
// BM=BN=128, BK=32, 3-stage cp.async, 8 warps (2x4), warp tile 64x32.
#define SA_LD 40
#define SB_LD 136
#define STAGE_H (2*128*SA_LD + 32*SB_LD)   // 14592 halfs
#define GEMM_SMEM (3 * STAGE_H * 2)        // 87552 bytes

__device__ __forceinline__ void cp16(void* s, const void* g)
{
    uint32_t sa = (uint32_t)__cvta_generic_to_shared(s);
    asm volatile("cp.async.cg.shared.global [%0], [%1], 16;\n" :: "r"(sa), "l"(g));
}

__global__ void __launch_bounds__(256) gemm2_kernel(
    const __half* __restrict__ Ah, const __half* __restrict__ Al,
    const __half* __restrict__ B,
    float* __restrict__ C, const float* __restrict__ bias, int Nn, int K)
{
    extern __shared__ __half smh[];
    const int bm = blockIdx.y * 128;
    const int bn = blockIdx.x * 128;
    const int tid = threadIdx.x;
    const int warp = tid >> 5;
    const int wr = (warp >> 2) * 64;   // 0,64
    const int wc = (warp & 3) * 32;    // 0,32,64,96

    wmma::fragment<wmma::accumulator, 16, 16, 16, float> acc[4][2];
    #pragma unroll
    for (int i = 0; i < 4; i++)
        #pragma unroll
        for (int j = 0; j < 2; j++)
            wmma::fill_fragment(acc[i][j], 0.0f);

    auto load_st = [&](int kt) {
        __half* s = smh + (kt % 3) * STAGE_H;
        int k0 = kt << 5;
        #pragma unroll
        for (int it = 0; it < 2; ++it) {
            int v = tid + it * 256;              // A: 512 vectors of 8 halfs
            int r = v >> 2, c = (v & 3) << 3;
            size_t go = (size_t)(bm + r) * K + k0 + c;
            cp16(s + r * SA_LD + c,                Ah + go);
            cp16(s + 128 * SA_LD + r * SA_LD + c,  Al + go);
            int rb = v >> 4, cb = (v & 15) << 3;  // B: 512 vectors
            cp16(s + 2 * 128 * SA_LD + rb * SB_LD + cb,
                 B + (size_t)(k0 + rb) * Nn + bn + cb);
        }
        asm volatile("cp.async.commit_group;\n");
    };

    const int nt = K >> 5;
    load_st(0);
    load_st(1);

    for (int kt = 0; kt < nt; ++kt) {
        if (kt + 1 < nt)
            asm volatile("cp.async.wait_group 1;\n");
        else
            asm volatile("cp.async.wait_group 0;\n");
        __syncthreads();
        if (kt + 2 < nt) load_st(kt + 2);

        __half* s   = smh + (kt % 3) * STAGE_H;
        __half* sAh = s;
        __half* sAl = s + 128 * SA_LD;
        __half* sB  = s + 2 * 128 * SA_LD;

        #pragma unroll
        for (int kk = 0; kk < 32; kk += 16) {
            wmma::fragment<wmma::matrix_b, 16, 16, 16, __half, wmma::row_major> b[2];
            #pragma unroll
            for (int j = 0; j < 2; j++)
                wmma::load_matrix_sync(b[j], sB + kk * SB_LD + wc + j * 16, SB_LD);
            #pragma unroll
            for (int i = 0; i < 4; i++) {
                wmma::fragment<wmma::matrix_a, 16, 16, 16, __half, wmma::row_major> ah, al;
                wmma::load_matrix_sync(ah, sAh + (wr + i * 16) * SA_LD + kk, SA_LD);
                wmma::load_matrix_sync(al, sAl + (wr + i * 16) * SA_LD + kk, SA_LD);
                #pragma unroll
                for (int j = 0; j < 2; j++) {
                    wmma::mma_sync(acc[i][j], ah, b[j], acc[i][j]);
                    wmma::mma_sync(acc[i][j], al, b[j], acc[i][j]);
                }
            }
        }
        __syncthreads();
    }

    __shared__ float sbias[128];
    if (bias) {
        if (tid < 128) sbias[tid] = bias[bn + tid];
    } else {
        if (tid < 128) sbias[tid] = 0.f;
    }
    __syncthreads();
    #pragma unroll
    for (int i = 0; i < 4; i++)
        #pragma unroll
        for (int j = 0; j < 2; j++) {
            #pragma unroll
            for (int t = 0; t < acc[i][j].num_elements; t++) ;  // no-op keep
            wmma::store_matrix_sync(C + (size_t)(bm + wr + i * 16) * Nn + bn + wc + j * 16,
                                    acc[i][j], Nn, wmma::mem_row_major);
        }
    // bias add folded via second pass over the warp's tile (fp32, cheap)
    if (bias) {
        __syncthreads();
        for (int idx = tid; idx < 128 * 32; idx += 256) {
            int r = idx >> 3, c4 = (idx & 7) << 4;   // 16 floats? no:
        }
    }
}

// NOTE: bias handled separately below to keep epilogue simple.

__global__ void bias_add4_kernel(float* __restrict__ X, const float* __restrict__ b,
                                 int width, int total4)
{
    int idx = blockIdx.x * blockDim.x + threadIdx.x;
    if (idx >= total4) return;
    int c = (idx << 2) % width;
    float4 v = ((float4*)X)[idx];
    float4 bb = *(const float4*)(b + c);
    v.x += bb.x; v.y += bb.y; v.z += bb.z; v.w += bb.w;
    ((float4*)X)[idx] = v;
}

// ---------------- RoPE + bias (in place, fp32) ----------------
__global__ void rope_bias_kernel(float* __restrict__ X, const float* __restrict__ bias,
                                 int width, int total_pairs)
{
    int idx = blockIdx.x * blockDim.x + threadIdx.x;
    if (idx >= total_pairs) return;
    int ppr = width >> 1;
    int row = idx / ppr;
    int p = idx - row * ppr;
    int i = p & 63;
    int pos = row & (SEQ - 1);
    float freq = exp2f(-(float)i * 0.20762050593434293f);
    float ang = (float)pos * freq;
    float sv, cv;
    sincosf(ang, &sv, &cv);
    float2 q = *(float2*)(X + (size_t)row * width + 2 * p);
    float e = q.x + bias[2 * p];
    float o = q.y + bias[2 * p + 1];
    float2 r2 = make_float2(e * cv - o * sv, o * cv + e * sv);
    *(float2*)(X + (size_t)row * width + 2 * p) = r2;
}

// ---------------- flash attention (fp32, fp16 hi/lo output) ----------------
#define SKLD 132
#define ATT_SMEM ((64*128 + 64*SKLD + 64*128 + 64*64) * 4)

__global__ void __launch_bounds__(256) flash_attn_kernel(
    const float* __restrict__ Q, const float* __restrict__ K,
    const float* __restrict__ V,
    __half* __restrict__ Ohi, __half* __restrict__ Olo)
{
    extern __shared__ float sm[];
    float* sQ = sm;
    float* sK = sQ + 64 * 128;
    float* sV = sK + 64 * SKLD;
    float* sP = sV + 64 * 128;

    const int b = blockIdx.y >> 5;
    const int h = blockIdx.y & 31;
    const int kh = h & 3;
    const int q0 = blockIdx.x * 64;
    const int tid = threadIdx.x;
    const int lane = tid & 31;
    const int warp = tid >> 5;
    const float scale = 0.08838834764831843f;

    for (int idx = tid; idx < 64 * 32; idx += 256) {
        int r = idx >> 5, c4 = (idx & 31) << 2;
        float4 v = *(const float4*)(Q + ((size_t)(b * SEQ + q0 + r)) * DMODEL + h * HDIM + c4);
        v.x *= scale; v.y *= scale; v.z *= scale; v.w *= scale;
        *(float4*)(sQ + r * 128 + c4) = v;
    }

    float acc[8][4];
    float mrow[8], lrow[8];
    #pragma unroll
    for (int i = 0; i < 8; i++) {
        mrow[i] = -1e30f; lrow[i] = 0.f;
        acc[i][0] = acc[i][1] = acc[i][2] = acc[i][3] = 0.f;
    }

    for (int j = 0; j <= blockIdx.x; ++j) {
        const int k0 = j * 64;
        __syncthreads();
        for (int idx = tid; idx < 64 * 32; idx += 256) {
            int r = idx >> 5, c4 = (idx & 31) << 2;
            size_t off = ((size_t)(b * SEQ + k0 + r)) * KVDIM + kh * HDIM + c4;
            *(float4*)(sK + r * SKLD + c4) = *(const float4*)(K + off);
            *(float4*)(sV + r * 128 + c4) = *(const float4*)(V + off);
        }
        __syncthreads();

        float s0[8], s1[8];
        #pragma unroll
        for (int i = 0; i < 8; i++) { s0[i] = 0.f; s1[i] = 0.f; }
        #pragma unroll 2
        for (int k = 0; k < 128; k += 4) {
            float4 ka = *(float4*)(sK + lane * SKLD + k);
            float4 kb = *(float4*)(sK + (lane + 32) * SKLD + k);
            #pragma unroll
            for (int i = 0; i < 8; i++) {
                float4 qv = *(float4*)(sQ + (warp * 8 + i) * 128 + k);
                s0[i] += qv.x * ka.x + qv.y * ka.y + qv.z * ka.z + qv.w * ka.w;
                s1[i] += qv.x * kb.x + qv.y * kb.y + qv.z * kb.z + qv.w * kb.w;
            }
        }
        if (j == blockIdx.x) {
            #pragma unroll
            for (int i = 0; i < 8; i++) {
                int qr = warp * 8 + i;
                if (lane > qr)      s0[i] = -1e30f;
                if (lane + 32 > qr) s1[i] = -1e30f;
            }
        }
        #pragma unroll
        for (int i = 0; i < 8; i++) {
            float mx = fmaxf(s0[i], s1[i]);
            #pragma unroll
            for (int off = 16; off; off >>= 1)
                mx = fmaxf(mx, __shfl_xor_sync(0xffffffffu, mx, off));
            float mnew = fmaxf(mrow[i], mx);
            float p0 = __expf(s0[i] - mnew);
            float p1 = __expf(s1[i] - mnew);
            float alpha = __expf(mrow[i] - mnew);
            mrow[i] = mnew;
            float ps = p0 + p1;
            #pragma unroll
            for (int off = 16; off; off >>= 1)
                ps += __shfl_xor_sync(0xffffffffu, ps, off);
            lrow[i] = lrow[i] * alpha + ps;
            acc[i][0] *= alpha; acc[i][1] *= alpha;
            acc[i][2] *= alpha; acc[i][3] *= alpha;
            sP[(warp * 8 + i) * 64 + lane] = p0;
            sP[(warp * 8 + i) * 64 + lane + 32] = p1;
        }
        __syncthreads();
        for (int c = 0; c < 64; c++) {
            float4 vv = *(float4*)(sV + c * 128 + lane * 4);
            #pragma unroll
            for (int i = 0; i < 8; i++) {
                float p = sP[(warp * 8 + i) * 64 + c];
                acc[i][0] += p * vv.x; acc[i][1] += p * vv.y;
                acc[i][2] += p * vv.z; acc[i][3] += p * vv.w;
            }
        }
    }

    #pragma unroll
    for (int i = 0; i < 8; i++) {
        float inv = 1.f / lrow[i];
        float o0 = acc[i][0] * inv, o1 = acc[i][1] * inv;
        float o2 = acc[i][2] * inv, o3 = acc[i][3] * inv;
        int r = q0 + warp * 8 + i;
        size_t off = ((size_t)(b * SEQ + r)) * DMODEL + h * HDIM + lane * 4;
        __half h0 = __float2half(o0), h1 = __float2half(o1);
        __half h2 = __float2half(o2), h3 = __float2half(o3);
        ((__half2*)(Ohi + off))[0] = __halves2half2(h0, h1);
        ((__half2*)(Ohi + off))[1] = __halves2half2(h2, h3);
        ((__half2*)(Olo + off))[0] = __halves2half2(
            __float2half(o0 - __half2float(h0)), __float2half(o1 - __half2float(h1)));
        ((__half2*)(Olo + off))[1] = __halves2half2(
            __float2half(o2 - __half2float(h2)), __float2half(o3 - __half2float(h3)));
    }
}

// ---------------- launch ----------------
extern "C" void kernel_launch(void* const* d_in, const int* in_sizes, int n_in,
                              void* d_out, int out_size)
{
    const float* x  = (const float*)d_in[0];
    const float* Wq = (const float*)d_in[1];
    const float* bq = (const float*)d_in[2];
    const float* Wk = (const float*)d_in[3];
    const float* bk = (const float*)d_in[4];
    const float* Wv = (const float*)d_in[5];
    const float* bv = (const float*)d_in[6];
    const float* Wo = (const float*)d_in[7];
    const float* bo = (const float*)d_in[8];
    float* out = (float*)d_out;

    float *Qp, *Kp, *Vp;
    __half *xh, *xl, *wq, *wk, *wv, *wo, *oh, *ol;
    cudaGetSymbolAddress((void**)&Qp, g_Q);
    cudaGetSymbolAddress((void**)&Kp, g_K);
    cudaGetSymbolAddress((void**)&Vp, g_V);
    cudaGetSymbolAddress((void**)&xh, g_xh); cudaGetSymbolAddress((void**)&xl, g_xl);
    cudaGetSymbolAddress((void**)&wq, g_wq); cudaGetSymbolAddress((void**)&wk, g_wk);
    cudaGetSymbolAddress((void**)&wv, g_wv); cudaGetSymbolAddress((void**)&wo, g_wo);
    cudaGetSymbolAddress((void**)&oh, g_oh); cudaGetSymbolAddress((void**)&ol, g_ol);

    cudaFuncSetAttribute(gemm2_kernel, cudaFuncAttributeMaxDynamicSharedMemorySize, GEMM_SMEM);
    cudaFuncSetAttribute(flash_attn_kernel, cudaFuncAttributeMaxDynamicSharedMemorySize, ATT_SMEM);

    // one-time conversions
    {
        int n4 = MROWS * DMODEL / 4;
        split_half_kernel<<<(n4 + 255) / 256, 256>>>(x, xh, xl, n4);
        n4 = DMODEL * DMODEL / 4;
        conv_half_kernel<<<(n4 + 255) / 256, 256>>>(Wq, wq, n4);
        conv_half_kernel<<<(n4 + 255) / 256, 256>>>(Wo, wo, n4);
        n4 = DMODEL * KVDIM / 4;
        conv_half_kernel<<<(n4 + 255) / 256, 256>>>(Wk, wk, n4);
        conv_half_kernel<<<(n4 + 255) / 256, 256>>>(Wv, wv, n4);
    }

    // projections
    gemm2_kernel<<<dim3(DMODEL / 128, MROWS / 128), 256, GEMM_SMEM>>>(
        xh, xl, wq, Qp, nullptr, DMODEL, DMODEL);
    gemm2_kernel<<<dim3(KVDIM / 128, MROWS / 128), 256, GEMM_SMEM>>>(
        xh, xl, wk, Kp, nullptr, KVDIM, DMODEL);
    gemm2_kernel<<<dim3(KVDIM / 128, MROWS / 128), 256, GEMM_SMEM>>>(
        xh, xl, wv, Vp, nullptr, KVDIM, DMODEL);

    // bias + RoPE for Q/K, bias for V
    {
        int tpQ = MROWS * (DMODEL / 2);
        rope_bias_kernel<<<(tpQ + 255) / 256, 256>>>(Qp, bq, DMODEL, tpQ);
        int tpK = MROWS * (KVDIM / 2);
        rope_bias_kernel<<<(tpK + 255) / 256, 256>>>(Kp, bk, KVDIM, tpK);
        int t4 = MROWS * KVDIM / 4;
        bias_add4_kernel<<<(t4 + 255) / 256, 256>>>(Vp, bv, KVDIM, t4);
    }

    // attention
    flash_attn_kernel<<<dim3(SEQ / 64, BATCH * NHEAD), 256, ATT_SMEM>>>(Qp, Kp, Vp, oh, ol);

    // output projection + bias
    gemm2_kernel<<<dim3(DMODEL / 128, MROWS / 128), 256, GEMM_SMEM>>>(
        oh, ol, wo, out, nullptr, DMODEL, DMODEL);
    {
        int t4 = MROWS * DMODEL / 4;
        bias_add4_kernel<<<(t4 + 255) / 256, 256>>>(out, bo, DMODEL, t4);
    }
}

// round 6
// speedup vs baseline: 2.3484x; 1.3162x over previous
#include <cuda_runtime.h>
#include <cuda_fp16.h>
#include <math.h>
#include <stdint.h>
#include <mma.h>

using namespace nvcuda;

#define BATCH 4
#define SEQ   1024
#define DMODEL 4096
#define KVDIM 512
#define NHEAD 32
#define HDIM  128
#define MROWS (BATCH*SEQ)   // 4096

// ---------------- scratch ----------------
__device__ float g_Q[MROWS * DMODEL];
__device__ float g_K[MROWS * KVDIM];
__device__ float g_V[MROWS * KVDIM];
__device__ __half g_x[MROWS * DMODEL];
__device__ __half g_wq[DMODEL * DMODEL];
__device__ __half g_wk[DMODEL * KVDIM];
__device__ __half g_wv[DMODEL * KVDIM];
__device__ __half g_wo[DMODEL * DMODEL];
__device__ __half g_o[MROWS * DMODEL];

// ---------------- fp32 -> fp16 ----------------
__global__ void conv_half_kernel(const float* __restrict__ src,
                                 __half* __restrict__ dst, int n4)
{
    int idx = blockIdx.x * blockDim.x + threadIdx.x;
    if (idx >= n4) return;
    float4 v = ((const float4*)src)[idx];
    ((__half2*)dst)[idx * 2]     = __halves2half2(__float2half(v.x), __float2half(v.y));
    ((__half2*)dst)[idx * 2 + 1] = __halves2half2(__float2half(v.z), __float2half(v.w));
}

// ---------------- fp16 GEMM: C = A[M,K] * B[K,N], fp32 acc ----------------
// BM=BN=128, BK=32, 3-stage cp.async, 8 warps (2x4), warp tile 64x32.
#define SA_LD 40
#define SB_LD 136
#define STAGE_H (128*SA_LD + 32*SB_LD)     // 9472 halfs
#define GEMM_SMEM (3 * STAGE_H * 2)        // 56832 bytes

__device__ __forceinline__ void cp16(void* s, const void* g)
{
    uint32_t sa = (uint32_t)__cvta_generic_to_shared(s);
    asm volatile("cp.async.cg.shared.global [%0], [%1], 16;\n" :: "r"(sa), "l"(g));
}

__global__ void __launch_bounds__(256) gemm1_kernel(
    const __half* __restrict__ A, const __half* __restrict__ B,
    float* __restrict__ C, int Nn, int K)
{
    extern __shared__ __half smh[];
    const int bm = blockIdx.y * 128;
    const int bn = blockIdx.x * 128;
    const int tid = threadIdx.x;
    const int warp = tid >> 5;
    const int wr = (warp >> 2) * 64;   // 0,64
    const int wc = (warp & 3) * 32;    // 0,32,64,96

    wmma::fragment<wmma::accumulator, 16, 16, 16, float> acc[4][2];
    #pragma unroll
    for (int i = 0; i < 4; i++)
        #pragma unroll
        for (int j = 0; j < 2; j++)
            wmma::fill_fragment(acc[i][j], 0.0f);

    auto load_st = [&](int kt) {
        __half* s = smh + (kt % 3) * STAGE_H;
        int k0 = kt << 5;
        #pragma unroll
        for (int it = 0; it < 2; ++it) {
            int v = tid + it * 256;
            int r = v >> 2, c = (v & 3) << 3;     // A: 128 x 32
            cp16(s + r * SA_LD + c, A + (size_t)(bm + r) * K + k0 + c);
            int rb = v >> 4, cb = (v & 15) << 3;  // B: 32 x 128
            cp16(s + 128 * SA_LD + rb * SB_LD + cb,
                 B + (size_t)(k0 + rb) * Nn + bn + cb);
        }
        asm volatile("cp.async.commit_group;\n");
    };

    const int nt = K >> 5;
    load_st(0);
    load_st(1);

    for (int kt = 0; kt < nt; ++kt) {
        if (kt + 1 < nt)
            asm volatile("cp.async.wait_group 1;\n");
        else
            asm volatile("cp.async.wait_group 0;\n");
        __syncthreads();
        if (kt + 2 < nt) load_st(kt + 2);

        __half* s  = smh + (kt % 3) * STAGE_H;
        __half* sA = s;
        __half* sB = s + 128 * SA_LD;

        #pragma unroll
        for (int kk = 0; kk < 32; kk += 16) {
            wmma::fragment<wmma::matrix_b, 16, 16, 16, __half, wmma::row_major> b[2];
            #pragma unroll
            for (int j = 0; j < 2; j++)
                wmma::load_matrix_sync(b[j], sB + kk * SB_LD + wc + j * 16, SB_LD);
            #pragma unroll
            for (int i = 0; i < 4; i++) {
                wmma::fragment<wmma::matrix_a, 16, 16, 16, __half, wmma::row_major> a;
                wmma::load_matrix_sync(a, sA + (wr + i * 16) * SA_LD + kk, SA_LD);
                #pragma unroll
                for (int j = 0; j < 2; j++)
                    wmma::mma_sync(acc[i][j], a, b[j], acc[i][j]);
            }
        }
        __syncthreads();
    }

    #pragma unroll
    for (int i = 0; i < 4; i++)
        #pragma unroll
        for (int j = 0; j < 2; j++)
            wmma::store_matrix_sync(C + (size_t)(bm + wr + i * 16) * Nn + bn + wc + j * 16,
                                    acc[i][j], Nn, wmma::mem_row_major);
}

// ---------------- bias add ----------------
__global__ void bias_add4_kernel(float* __restrict__ X, const float* __restrict__ b,
                                 int width, int total4)
{
    int idx = blockIdx.x * blockDim.x + threadIdx.x;
    if (idx >= total4) return;
    int c = (idx << 2) % width;
    float4 v = ((float4*)X)[idx];
    float4 bb = *(const float4*)(b + c);
    v.x += bb.x; v.y += bb.y; v.z += bb.z; v.w += bb.w;
    ((float4*)X)[idx] = v;
}

// ---------------- RoPE + bias (in place, fp32) ----------------
__global__ void rope_bias_kernel(float* __restrict__ X, const float* __restrict__ bias,
                                 int width, int total_pairs)
{
    int idx = blockIdx.x * blockDim.x + threadIdx.x;
    if (idx >= total_pairs) return;
    int ppr = width >> 1;
    int row = idx / ppr;
    int p = idx - row * ppr;
    int i = p & 63;
    int pos = row & (SEQ - 1);
    float freq = exp2f(-(float)i * 0.20762050593434293f);
    float ang = (float)pos * freq;
    float sv, cv;
    sincosf(ang, &sv, &cv);
    float2 q = *(float2*)(X + (size_t)row * width + 2 * p);
    float e = q.x + bias[2 * p];
    float o = q.y + bias[2 * p + 1];
    float2 r2 = make_float2(e * cv - o * sv, o * cv + e * sv);
    *(float2*)(X + (size_t)row * width + 2 * p) = r2;
}

// ---------------- flash attention (fp32, fp16 output) ----------------
#define SKLD 132
#define ATT_SMEM ((64*128 + 64*SKLD + 64*128 + 64*64) * 4)

__global__ void __launch_bounds__(256) flash_attn_kernel(
    const float* __restrict__ Q, const float* __restrict__ K,
    const float* __restrict__ V, __half* __restrict__ O)
{
    extern __shared__ float sm[];
    float* sQ = sm;
    float* sK = sQ + 64 * 128;
    float* sV = sK + 64 * SKLD;
    float* sP = sV + 64 * 128;

    const int b = blockIdx.y >> 5;
    const int h = blockIdx.y & 31;
    const int kh = h & 3;
    const int q0 = blockIdx.x * 64;
    const int tid = threadIdx.x;
    const int lane = tid & 31;
    const int warp = tid >> 5;
    const float scale = 0.08838834764831843f;

    for (int idx = tid; idx < 64 * 32; idx += 256) {
        int r = idx >> 5, c4 = (idx & 31) << 2;
        float4 v = *(const float4*)(Q + ((size_t)(b * SEQ + q0 + r)) * DMODEL + h * HDIM + c4);
        v.x *= scale; v.y *= scale; v.z *= scale; v.w *= scale;
        *(float4*)(sQ + r * 128 + c4) = v;
    }

    float acc[8][4];
    float mrow[8], lrow[8];
    #pragma unroll
    for (int i = 0; i < 8; i++) {
        mrow[i] = -1e30f; lrow[i] = 0.f;
        acc[i][0] = acc[i][1] = acc[i][2] = acc[i][3] = 0.f;
    }

    for (int j = 0; j <= blockIdx.x; ++j) {
        const int k0 = j * 64;
        __syncthreads();
        for (int idx = tid; idx < 64 * 32; idx += 256) {
            int r = idx >> 5, c4 = (idx & 31) << 2;
            size_t off = ((size_t)(b * SEQ + k0 + r)) * KVDIM + kh * HDIM + c4;
            *(float4*)(sK + r * SKLD + c4) = *(const float4*)(K + off);
            *(float4*)(sV + r * 128 + c4) = *(const float4*)(V + off);
        }
        __syncthreads();

        float s0[8], s1[8];
        #pragma unroll
        for (int i = 0; i < 8; i++) { s0[i] = 0.f; s1[i] = 0.f; }
        #pragma unroll 2
        for (int k = 0; k < 128; k += 4) {
            float4 ka = *(float4*)(sK + lane * SKLD + k);
            float4 kb = *(float4*)(sK + (lane + 32) * SKLD + k);
            #pragma unroll
            for (int i = 0; i < 8; i++) {
                float4 qv = *(float4*)(sQ + (warp * 8 + i) * 128 + k);
                s0[i] += qv.x * ka.x + qv.y * ka.y + qv.z * ka.z + qv.w * ka.w;
                s1[i] += qv.x * kb.x + qv.y * kb.y + qv.z * kb.z + qv.w * kb.w;
            }
        }
        if (j == blockIdx.x) {
            #pragma unroll
            for (int i = 0; i < 8; i++) {
                int qr = warp * 8 + i;
                if (lane > qr)      s0[i] = -1e30f;
                if (lane + 32 > qr) s1[i] = -1e30f;
            }
        }
        #pragma unroll
        for (int i = 0; i < 8; i++) {
            float mx = fmaxf(s0[i], s1[i]);
            #pragma unroll
            for (int off = 16; off; off >>= 1)
                mx = fmaxf(mx, __shfl_xor_sync(0xffffffffu, mx, off));
            float mnew = fmaxf(mrow[i], mx);
            float p0 = __expf(s0[i] - mnew);
            float p1 = __expf(s1[i] - mnew);
            float alpha = __expf(mrow[i] - mnew);
            mrow[i] = mnew;
            float ps = p0 + p1;
            #pragma unroll
            for (int off = 16; off; off >>= 1)
                ps += __shfl_xor_sync(0xffffffffu, ps, off);
            lrow[i] = lrow[i] * alpha + ps;
            acc[i][0] *= alpha; acc[i][1] *= alpha;
            acc[i][2] *= alpha; acc[i][3] *= alpha;
            sP[(warp * 8 + i) * 64 + lane] = p0;
            sP[(warp * 8 + i) * 64 + lane + 32] = p1;
        }
        __syncthreads();
        for (int c = 0; c < 64; c++) {
            float4 vv = *(float4*)(sV + c * 128 + lane * 4);
            #pragma unroll
            for (int i = 0; i < 8; i++) {
                float p = sP[(warp * 8 + i) * 64 + c];
                acc[i][0] += p * vv.x; acc[i][1] += p * vv.y;
                acc[i][2] += p * vv.z; acc[i][3] += p * vv.w;
            }
        }
    }

    #pragma unroll
    for (int i = 0; i < 8; i++) {
        float inv = 1.f / lrow[i];
        int r = q0 + warp * 8 + i;
        size_t off = ((size_t)(b * SEQ + r)) * DMODEL + h * HDIM + lane * 4;
        ((__half2*)(O + off))[0] = __halves2half2(
            __float2half(acc[i][0] * inv), __float2half(acc[i][1] * inv));
        ((__half2*)(O + off))[1] = __halves2half2(
            __float2half(acc[i][2] * inv), __float2half(acc[i][3] * inv));
    }
}

// ---------------- launch ----------------
extern "C" void kernel_launch(void* const* d_in, const int* in_sizes, int n_in,
                              void* d_out, int out_size)
{
    const float* x  = (const float*)d_in[0];
    const float* Wq = (const float*)d_in[1];
    const float* bq = (const float*)d_in[2];
    const float* Wk = (const float*)d_in[3];
    const float* bk = (const float*)d_in[4];
    const float* Wv = (const float*)d_in[5];
    const float* bv = (const float*)d_in[6];
    const float* Wo = (const float*)d_in[7];
    const float* bo = (const float*)d_in[8];
    float* out = (float*)d_out;

    float *Qp, *Kp, *Vp;
    __half *xp, *wq, *wk, *wv, *wo, *op;
    cudaGetSymbolAddress((void**)&Qp, g_Q);
    cudaGetSymbolAddress((void**)&Kp, g_K);
    cudaGetSymbolAddress((void**)&Vp, g_V);
    cudaGetSymbolAddress((void**)&xp, g_x);
    cudaGetSymbolAddress((void**)&wq, g_wq); cudaGetSymbolAddress((void**)&wk, g_wk);
    cudaGetSymbolAddress((void**)&wv, g_wv); cudaGetSymbolAddress((void**)&wo, g_wo);
    cudaGetSymbolAddress((void**)&op, g_o);

    cudaFuncSetAttribute(gemm1_kernel, cudaFuncAttributeMaxDynamicSharedMemorySize, GEMM_SMEM);
    cudaFuncSetAttribute(flash_attn_kernel, cudaFuncAttributeMaxDynamicSharedMemorySize, ATT_SMEM);

    // one-time conversions
    {
        int n4 = MROWS * DMODEL / 4;
        conv_half_kernel<<<(n4 + 255) / 256, 256>>>(x, xp, n4);
        n4 = DMODEL * DMODEL / 4;
        conv_half_kernel<<<(n4 + 255) / 256, 256>>>(Wq, wq, n4);
        conv_half_kernel<<<(n4 + 255) / 256, 256>>>(Wo, wo, n4);
        n4 = DMODEL * KVDIM / 4;
        conv_half_kernel<<<(n4 + 255) / 256, 256>>>(Wk, wk, n4);
        conv_half_kernel<<<(n4 + 255) / 256, 256>>>(Wv, wv, n4);
    }

    // projections
    gemm1_kernel<<<dim3(DMODEL / 128, MROWS / 128), 256, GEMM_SMEM>>>(xp, wq, Qp, DMODEL, DMODEL);
    gemm1_kernel<<<dim3(KVDIM / 128, MROWS / 128), 256, GEMM_SMEM>>>(xp, wk, Kp, KVDIM, DMODEL);
    gemm1_kernel<<<dim3(KVDIM / 128, MROWS / 128), 256, GEMM_SMEM>>>(xp, wv, Vp, KVDIM, DMODEL);

    // bias + RoPE for Q/K, bias for V
    {
        int tpQ = MROWS * (DMODEL / 2);
        rope_bias_kernel<<<(tpQ + 255) / 256, 256>>>(Qp, bq, DMODEL, tpQ);
        int tpK = MROWS * (KVDIM / 2);
        rope_bias_kernel<<<(tpK + 255) / 256, 256>>>(Kp, bk, KVDIM, tpK);
        int t4 = MROWS * KVDIM / 4;
        bias_add4_kernel<<<(t4 + 255) / 256, 256>>>(Vp, bv, KVDIM, t4);
    }

    // attention
    flash_attn_kernel<<<dim3(SEQ / 64, BATCH * NHEAD), 256, ATT_SMEM>>>(Qp, Kp, Vp, op);

    // output projection + bias
    gemm1_kernel<<<dim3(DMODEL / 128, MROWS / 128), 256, GEMM_SMEM>>>(op, wo, out, DMODEL, DMODEL);
    {
        int t4 = MROWS * DMODEL / 4;
        bias_add4_kernel<<<(t4 + 255) / 256, 256>>>(out, bo, DMODEL, t4);
    }
}

// round 7
// speedup vs baseline: 2.8334x; 1.2065x over previous
#include <cuda_runtime.h>
#include <cuda_fp16.h>
#include <math.h>
#include <stdint.h>
#include <mma.h>

using namespace nvcuda;

#define BATCH 4
#define SEQ   1024
#define DMODEL 4096
#define KVDIM 512
#define NHEAD 32
#define HDIM  128
#define MROWS (BATCH*SEQ)   // 4096

// ---------------- scratch ----------------
__device__ float g_Q[MROWS * DMODEL];
__device__ float g_K[MROWS * KVDIM];
__device__ float g_V[MROWS * KVDIM];
__device__ __half g_x[MROWS * DMODEL];
__device__ __half g_wq[DMODEL * DMODEL];
__device__ __half g_wk[DMODEL * KVDIM];
__device__ __half g_wv[DMODEL * KVDIM];
__device__ __half g_wo[DMODEL * DMODEL];
__device__ __half g_Qh[MROWS * DMODEL], g_Ql[MROWS * DMODEL];
__device__ __half g_Kh[MROWS * KVDIM];
__device__ __half g_Vh[MROWS * KVDIM];
__device__ __half g_o[MROWS * DMODEL];

// ---------------- fp32 -> fp16 ----------------
__global__ void conv_half_kernel(const float* __restrict__ src,
                                 __half* __restrict__ dst, int n4)
{
    int idx = blockIdx.x * blockDim.x + threadIdx.x;
    if (idx >= n4) return;
    float4 v = ((const float4*)src)[idx];
    ((__half2*)dst)[idx * 2]     = __halves2half2(__float2half(v.x), __float2half(v.y));
    ((__half2*)dst)[idx * 2 + 1] = __halves2half2(__float2half(v.z), __float2half(v.w));
}

// ---------------- fp16 GEMM: C = A[M,K] * B[K,N], fp32 acc ----------------
#define SA_LD 40
#define SB_LD 136
#define STAGE_H (128*SA_LD + 32*SB_LD)
#define GEMM_SMEM (3 * STAGE_H * 2)

__device__ __forceinline__ void cp16(void* s, const void* g)
{
    uint32_t sa = (uint32_t)__cvta_generic_to_shared(s);
    asm volatile("cp.async.cg.shared.global [%0], [%1], 16;\n" :: "r"(sa), "l"(g));
}

__global__ void __launch_bounds__(256) gemm1_kernel(
    const __half* __restrict__ A, const __half* __restrict__ B,
    float* __restrict__ C, int Nn, int K)
{
    extern __shared__ __half smh[];
    const int bm = blockIdx.y * 128;
    const int bn = blockIdx.x * 128;
    const int tid = threadIdx.x;
    const int warp = tid >> 5;
    const int wr = (warp >> 2) * 64;
    const int wc = (warp & 3) * 32;

    wmma::fragment<wmma::accumulator, 16, 16, 16, float> acc[4][2];
    #pragma unroll
    for (int i = 0; i < 4; i++)
        #pragma unroll
        for (int j = 0; j < 2; j++)
            wmma::fill_fragment(acc[i][j], 0.0f);

    auto load_st = [&](int kt) {
        __half* s = smh + (kt % 3) * STAGE_H;
        int k0 = kt << 5;
        #pragma unroll
        for (int it = 0; it < 2; ++it) {
            int v = tid + it * 256;
            int r = v >> 2, c = (v & 3) << 3;
            cp16(s + r * SA_LD + c, A + (size_t)(bm + r) * K + k0 + c);
            int rb = v >> 4, cb = (v & 15) << 3;
            cp16(s + 128 * SA_LD + rb * SB_LD + cb,
                 B + (size_t)(k0 + rb) * Nn + bn + cb);
        }
        asm volatile("cp.async.commit_group;\n");
    };

    const int nt = K >> 5;
    load_st(0);
    load_st(1);

    for (int kt = 0; kt < nt; ++kt) {
        if (kt + 1 < nt)
            asm volatile("cp.async.wait_group 1;\n");
        else
            asm volatile("cp.async.wait_group 0;\n");
        __syncthreads();
        if (kt + 2 < nt) load_st(kt + 2);

        __half* s  = smh + (kt % 3) * STAGE_H;
        __half* sA = s;
        __half* sB = s + 128 * SA_LD;

        #pragma unroll
        for (int kk = 0; kk < 32; kk += 16) {
            wmma::fragment<wmma::matrix_b, 16, 16, 16, __half, wmma::row_major> b[2];
            #pragma unroll
            for (int j = 0; j < 2; j++)
                wmma::load_matrix_sync(b[j], sB + kk * SB_LD + wc + j * 16, SB_LD);
            #pragma unroll
            for (int i = 0; i < 4; i++) {
                wmma::fragment<wmma::matrix_a, 16, 16, 16, __half, wmma::row_major> a;
                wmma::load_matrix_sync(a, sA + (wr + i * 16) * SA_LD + kk, SA_LD);
                #pragma unroll
                for (int j = 0; j < 2; j++)
                    wmma::mma_sync(acc[i][j], a, b[j], acc[i][j]);
            }
        }
        __syncthreads();
    }

    #pragma unroll
    for (int i = 0; i < 4; i++)
        #pragma unroll
        for (int j = 0; j < 2; j++)
            wmma::store_matrix_sync(C + (size_t)(bm + wr + i * 16) * Nn + bn + wc + j * 16,
                                    acc[i][j], Nn, wmma::mem_row_major);
}

// ---------------- bias add (fp32 in place) ----------------
__global__ void bias_add4_kernel(float* __restrict__ X, const float* __restrict__ b,
                                 int width, int total4)
{
    int idx = blockIdx.x * blockDim.x + threadIdx.x;
    if (idx >= total4) return;
    int c = (idx << 2) % width;
    float4 v = ((float4*)X)[idx];
    float4 bb = *(const float4*)(b + c);
    v.x += bb.x; v.y += bb.y; v.z += bb.z; v.w += bb.w;
    ((float4*)X)[idx] = v;
}

// ---------------- RoPE + bias -> fp16 hi/lo (for Q) ----------------
__global__ void rope_q_kernel(const float* __restrict__ X, const float* __restrict__ bias,
                              __half* __restrict__ Oh, __half* __restrict__ Ol,
                              int width, float scale, int total_pairs)
{
    int idx = blockIdx.x * blockDim.x + threadIdx.x;
    if (idx >= total_pairs) return;
    int ppr = width >> 1;
    int row = idx / ppr;
    int p = idx - row * ppr;
    int i = p & 63;
    int pos = row & (SEQ - 1);
    float freq = exp2f(-(float)i * 0.20762050593434293f);
    float ang = (float)pos * freq;
    float sv, cv;
    sincosf(ang, &sv, &cv);
    float2 q = *(const float2*)(X + (size_t)row * width + 2 * p);
    float e = q.x + bias[2 * p];
    float o = q.y + bias[2 * p + 1];
    float re = (e * cv - o * sv) * scale;
    float ro = (o * cv + e * sv) * scale;
    __half he = __float2half(re), ho = __float2half(ro);
    size_t off = (size_t)row * width + 2 * p;
    *(__half2*)(Oh + off) = __halves2half2(he, ho);
    *(__half2*)(Ol + off) = __halves2half2(
        __float2half(re - __half2float(he)), __float2half(ro - __half2float(ho)));
}

// ---------------- RoPE + bias -> fp16 (for K) ----------------
__global__ void rope_k_kernel(const float* __restrict__ X, const float* __restrict__ bias,
                              __half* __restrict__ O, int width, int total_pairs)
{
    int idx = blockIdx.x * blockDim.x + threadIdx.x;
    if (idx >= total_pairs) return;
    int ppr = width >> 1;
    int row = idx / ppr;
    int p = idx - row * ppr;
    int i = p & 63;
    int pos = row & (SEQ - 1);
    float freq = exp2f(-(float)i * 0.20762050593434293f);
    float ang = (float)pos * freq;
    float sv, cv;
    sincosf(ang, &sv, &cv);
    float2 q = *(const float2*)(X + (size_t)row * width + 2 * p);
    float e = q.x + bias[2 * p];
    float o = q.y + bias[2 * p + 1];
    *(__half2*)(O + (size_t)row * width + 2 * p) = __halves2half2(
        __float2half(e * cv - o * sv), __float2half(o * cv + e * sv));
}

// ---------------- bias -> fp16 (for V) ----------------
__global__ void bias_h_kernel(const float* __restrict__ X, const float* __restrict__ b,
                              __half* __restrict__ O, int width, int total4)
{
    int idx = blockIdx.x * blockDim.x + threadIdx.x;
    if (idx >= total4) return;
    int c = (idx << 2) % width;
    float4 v = ((const float4*)X)[idx];
    float4 bb = *(const float4*)(b + c);
    ((__half2*)O)[idx * 2]     = __halves2half2(__float2half(v.x + bb.x), __float2half(v.y + bb.y));
    ((__half2*)O)[idx * 2 + 1] = __halves2half2(__float2half(v.z + bb.z), __float2half(v.w + bb.w));
}

// ---------------- fast exp on FMA pipe ----------------
__device__ __forceinline__ float fexp(float x)
{
    float y = x * 1.4426950408889634f;
    float r = __fadd_rn(y, 12582912.0f);
    float n = __fadd_rn(r, -12582912.0f);
    float f = y - n;
    int e = __float2int_rn(n);
    e = max(e, -126); e = min(e, 126);
    float t = f * 0.6931471805599453f;
    float p = __fmaf_rn(t, 0.0083333333f, 0.041666667f);
    p = __fmaf_rn(t, p, 0.16666667f);
    p = __fmaf_rn(t, p, 0.5f);
    p = __fmaf_rn(t, p, 1.0f);
    p = __fmaf_rn(t, p, 1.0f);
    return p * __int_as_float((e + 127) << 23);
}

// ---------------- tensor-core flash attention ----------------
// 64 q-rows x 64 k-cols tiles, 128 threads (4 warps), fp32 softmax, fp16 MMA.
#define AQ_LD 136   // halfs (Q/K/V/T row stride)
#define AS_LD 72    // S/P row stride
#define OQH 0
#define OQL (OQH + 64*AQ_LD*2)
#define OKK (OQL + 64*AQ_LD*2)
#define OVV (OKK + 2*64*AQ_LD*2)
#define OPP (OVV + 2*64*AQ_LD*2)
#define OSS (OPP + 64*AS_LD*2)
#define OTT (OSS + 64*AS_LD*4)
#define OOO (OTT + 64*AQ_LD*4)
#define ATT_SMEM (OOO + 64*128*4)

__global__ void __launch_bounds__(128) attn_tc_kernel(
    const __half* __restrict__ Qh, const __half* __restrict__ Ql,
    const __half* __restrict__ K, const __half* __restrict__ V,
    __half* __restrict__ O)
{
    extern __shared__ char smc[];
    __half* sQh = (__half*)(smc + OQH);
    __half* sQl = (__half*)(smc + OQL);
    __half* sK  = (__half*)(smc + OKK);
    __half* sV  = (__half*)(smc + OVV);
    __half* sP  = (__half*)(smc + OPP);
    float*  sS  = (float*)(smc + OSS);
    float*  sT  = (float*)(smc + OTT);
    float*  sO  = (float*)(smc + OOO);

    const int b = blockIdx.y >> 5;
    const int h = blockIdx.y & 31;
    const int kh = h & 3;
    const int q0 = blockIdx.x * 64;
    const int tid = threadIdx.x;
    const int lane = tid & 31;
    const int warp = tid >> 5;

    // load Q tiles (hi/lo)
    for (int idx = tid; idx < 64 * 16; idx += 128) {
        int r = idx >> 4, c = (idx & 15) << 3;
        size_t go = (size_t)(b * SEQ + q0 + r) * DMODEL + h * HDIM + c;
        *(uint4*)(sQh + r * AQ_LD + c) = *(const uint4*)(Qh + go);
        *(uint4*)(sQl + r * AQ_LD + c) = *(const uint4*)(Ql + go);
    }
    // zero sO
    for (int idx = tid; idx < 64 * 128 / 4; idx += 128) {
        ((float4*)sO)[idx] = make_float4(0.f, 0.f, 0.f, 0.f);
    }

    auto prefetch = [&](int j) {
        int buf = j & 1;
        int k0 = j * 64;
        __half* dk = sK + buf * 64 * AQ_LD;
        __half* dv = sV + buf * 64 * AQ_LD;
        #pragma unroll
        for (int i = 0; i < 8; i++) {
            int idx = tid + i * 128;
            int r = idx >> 4, c = (idx & 15) << 3;
            size_t go = (size_t)(b * SEQ + k0 + r) * KVDIM + kh * HDIM + c;
            cp16(dk + r * AQ_LD + c, K + go);
            cp16(dv + r * AQ_LD + c, V + go);
        }
        asm volatile("cp.async.commit_group;\n");
    };

    prefetch(0);

    // per-thread softmax state: row = warp*16 + lane/2
    const int srow = warp * 16 + (lane >> 1);
    const int shalf = lane & 1;
    float mrow = -1e30f, lrow = 0.f;

    const int jmax = blockIdx.x;
    for (int j = 0; j <= jmax; ++j) {
        asm volatile("cp.async.wait_group 0;\n");
        __syncthreads();
        if (j + 1 <= jmax) prefetch(j + 1);

        __half* cK = sK + (j & 1) * 64 * AQ_LD;
        __half* cV = sV + (j & 1) * 64 * AQ_LD;

        // ---- S = Q K^T (hi + lo) ----
        {
            wmma::fragment<wmma::accumulator, 16, 16, 16, float> acc[4];
            #pragma unroll
            for (int nf = 0; nf < 4; nf++) wmma::fill_fragment(acc[nf], 0.f);
            #pragma unroll
            for (int ks = 0; ks < 8; ks++) {
                wmma::fragment<wmma::matrix_a, 16, 16, 16, __half, wmma::row_major> ah, al;
                wmma::load_matrix_sync(ah, sQh + warp * 16 * AQ_LD + ks * 16, AQ_LD);
                wmma::load_matrix_sync(al, sQl + warp * 16 * AQ_LD + ks * 16, AQ_LD);
                #pragma unroll
                for (int nf = 0; nf < 4; nf++) {
                    wmma::fragment<wmma::matrix_b, 16, 16, 16, __half, wmma::col_major> bf;
                    wmma::load_matrix_sync(bf, cK + nf * 16 * AQ_LD + ks * 16, AQ_LD);
                    wmma::mma_sync(acc[nf], ah, bf, acc[nf]);
                    wmma::mma_sync(acc[nf], al, bf, acc[nf]);
                }
            }
            #pragma unroll
            for (int nf = 0; nf < 4; nf++)
                wmma::store_matrix_sync(sS + warp * 16 * AS_LD + nf * 16, acc[nf],
                                        AS_LD, wmma::mem_row_major);
        }
        __syncthreads();

        // ---- softmax (online) ----
        {
            const int cbase = shalf * 32;
            const bool diag = (j == jmax);
            float sv[32];
            float mx = -1e30f;
            #pragma unroll
            for (int c = 0; c < 32; c++) {
                float s = sS[srow * AS_LD + cbase + c];
                if (diag && (cbase + c > srow)) s = -1e30f;
                sv[c] = s;
                mx = fmaxf(mx, s);
            }
            mx = fmaxf(mx, __shfl_xor_sync(0xffffffffu, mx, 1));
            float mnew = fmaxf(mrow, mx);
            float alpha = fexp(mrow - mnew);
            float sum = 0.f;
            #pragma unroll
            for (int c = 0; c < 32; c++) {
                float p = fexp(sv[c] - mnew);
                sP[srow * AS_LD + cbase + c] = __float2half(p);
                sum += p;
            }
            sum += __shfl_xor_sync(0xffffffffu, sum, 1);
            lrow = lrow * alpha + sum;
            mrow = mnew;
            // stash alpha for accumulate phase (keep in reg)
            sv[0] = alpha;  // avoid compiler complaints; alpha reused below
            __syncthreads();

            // ---- PV ----
            {
                wmma::fragment<wmma::accumulator, 16, 16, 16, float> acc[8];
                #pragma unroll
                for (int nf = 0; nf < 8; nf++) wmma::fill_fragment(acc[nf], 0.f);
                #pragma unroll
                for (int kf = 0; kf < 4; kf++) {
                    wmma::fragment<wmma::matrix_a, 16, 16, 16, __half, wmma::row_major> af;
                    wmma::load_matrix_sync(af, sP + warp * 16 * AS_LD + kf * 16, AS_LD);
                    #pragma unroll
                    for (int nf = 0; nf < 8; nf++) {
                        wmma::fragment<wmma::matrix_b, 16, 16, 16, __half, wmma::row_major> bf;
                        wmma::load_matrix_sync(bf, cV + kf * 16 * AQ_LD + nf * 16, AQ_LD);
                        wmma::mma_sync(acc[nf], af, bf, acc[nf]);
                    }
                }
                #pragma unroll
                for (int nf = 0; nf < 8; nf++)
                    wmma::store_matrix_sync(sT + warp * 16 * AQ_LD + nf * 16, acc[nf],
                                            AQ_LD, wmma::mem_row_major);
            }
            __syncthreads();

            // ---- O = O*alpha + T ----
            {
                const int c0 = shalf * 64;
                #pragma unroll
                for (int c = 0; c < 64; c += 4) {
                    float4 o = *(float4*)(sO + srow * 128 + c0 + c);
                    float4 t = *(float4*)(sT + srow * AQ_LD + c0 + c);
                    o.x = o.x * alpha + t.x; o.y = o.y * alpha + t.y;
                    o.z = o.z * alpha + t.z; o.w = o.w * alpha + t.w;
                    *(float4*)(sO + srow * 128 + c0 + c) = o;
                }
            }
            __syncthreads();
        }
    }

    // final write
    {
        float inv = 1.f / lrow;
        const int c0 = shalf * 64;
        size_t off = (size_t)(b * SEQ + q0 + srow) * DMODEL + h * HDIM + c0;
        #pragma unroll
        for (int c = 0; c < 64; c += 2) {
            float2 o = *(float2*)(sO + srow * 128 + c0 + c);
            *(__half2*)(O + off + c) = __halves2half2(
                __float2half(o.x * inv), __float2half(o.y * inv));
        }
    }
}

// ---------------- launch ----------------
extern "C" void kernel_launch(void* const* d_in, const int* in_sizes, int n_in,
                              void* d_out, int out_size)
{
    const float* x  = (const float*)d_in[0];
    const float* Wq = (const float*)d_in[1];
    const float* bq = (const float*)d_in[2];
    const float* Wk = (const float*)d_in[3];
    const float* bk = (const float*)d_in[4];
    const float* Wv = (const float*)d_in[5];
    const float* bv = (const float*)d_in[6];
    const float* Wo = (const float*)d_in[7];
    const float* bo = (const float*)d_in[8];
    float* out = (float*)d_out;

    float *Qp, *Kp, *Vp;
    __half *xp, *wq, *wk, *wv, *wo, *op, *qh, *ql, *kk, *vv;
    cudaGetSymbolAddress((void**)&Qp, g_Q);
    cudaGetSymbolAddress((void**)&Kp, g_K);
    cudaGetSymbolAddress((void**)&Vp, g_V);
    cudaGetSymbolAddress((void**)&xp, g_x);
    cudaGetSymbolAddress((void**)&wq, g_wq); cudaGetSymbolAddress((void**)&wk, g_wk);
    cudaGetSymbolAddress((void**)&wv, g_wv); cudaGetSymbolAddress((void**)&wo, g_wo);
    cudaGetSymbolAddress((void**)&op, g_o);
    cudaGetSymbolAddress((void**)&qh, g_Qh); cudaGetSymbolAddress((void**)&ql, g_Ql);
    cudaGetSymbolAddress((void**)&kk, g_Kh); cudaGetSymbolAddress((void**)&vv, g_Vh);

    cudaFuncSetAttribute(gemm1_kernel, cudaFuncAttributeMaxDynamicSharedMemorySize, GEMM_SMEM);
    cudaFuncSetAttribute(attn_tc_kernel, cudaFuncAttributeMaxDynamicSharedMemorySize, ATT_SMEM);

    // one-time conversions
    {
        int n4 = MROWS * DMODEL / 4;
        conv_half_kernel<<<(n4 + 255) / 256, 256>>>(x, xp, n4);
        n4 = DMODEL * DMODEL / 4;
        conv_half_kernel<<<(n4 + 255) / 256, 256>>>(Wq, wq, n4);
        conv_half_kernel<<<(n4 + 255) / 256, 256>>>(Wo, wo, n4);
        n4 = DMODEL * KVDIM / 4;
        conv_half_kernel<<<(n4 + 255) / 256, 256>>>(Wk, wk, n4);
        conv_half_kernel<<<(n4 + 255) / 256, 256>>>(Wv, wv, n4);
    }

    // projections
    gemm1_kernel<<<dim3(DMODEL / 128, MROWS / 128), 256, GEMM_SMEM>>>(xp, wq, Qp, DMODEL, DMODEL);
    gemm1_kernel<<<dim3(KVDIM / 128, MROWS / 128), 256, GEMM_SMEM>>>(xp, wk, Kp, KVDIM, DMODEL);
    gemm1_kernel<<<dim3(KVDIM / 128, MROWS / 128), 256, GEMM_SMEM>>>(xp, wv, Vp, KVDIM, DMODEL);

    // RoPE/bias -> fp16 attention operands
    {
        const float scale = 0.08838834764831843f;
        int tpQ = MROWS * (DMODEL / 2);
        rope_q_kernel<<<(tpQ + 255) / 256, 256>>>(Qp, bq, qh, ql, DMODEL, scale, tpQ);
        int tpK = MROWS * (KVDIM / 2);
        rope_k_kernel<<<(tpK + 255) / 256, 256>>>(Kp, bk, kk, KVDIM, tpK);
        int t4 = MROWS * KVDIM / 4;
        bias_h_kernel<<<(t4 + 255) / 256, 256>>>(Vp, bv, vv, KVDIM, t4);
    }

    // attention (tensor cores)
    attn_tc_kernel<<<dim3(SEQ / 64, BATCH * NHEAD), 128, ATT_SMEM>>>(qh, ql, kk, vv, op);

    // output projection + bias
    gemm1_kernel<<<dim3(DMODEL / 128, MROWS / 128), 256, GEMM_SMEM>>>(op, wo, out, DMODEL, DMODEL);
    {
        int t4 = MROWS * DMODEL / 4;
        bias_add4_kernel<<<(t4 + 255) / 256, 256>>>(out, bo, DMODEL, t4);
    }
}